// round 14
// baseline (speedup 1.0000x reference)
#include <cuda_runtime.h>
#include <cuda_bf16.h>
#include <cuda_fp16.h>
#include <math.h>
#include <stdint.h>

#define BATCH 2
#define CH    512
#define NH    8
#define HD    64
#define HW    4096
#define NG    8
#define CPG   64
#define EPS   1e-5f
#define LOG2E 1.4426950408889634f
#define QSCALE (0.125f * LOG2E)
#define MFIX  8.0f

// ---------------- scratch ----------------
__device__ __align__(128) __nv_bfloat16 g_xn[(size_t)BATCH*HW*CH];   // [b][n][c]
__device__ __align__(128) __nv_bfloat16 g_q[(size_t)BATCH*NH*HD*HW]; // [bh][d][n] scaled
__device__ __align__(128) __nv_bfloat16 g_k[(size_t)BATCH*NH*HD*HW]; // [bh][d][n]
__device__ __align__(128) __half        g_v[(size_t)BATCH*NH*HD*HW]; // [bh][d][n] fp16
__device__ __align__(128) __nv_bfloat16 g_o[(size_t)BATCH*HW*CH];    // [b][n][c]
__device__ __align__(128) __nv_bfloat16 g_wq[3*CH*CH];
__device__ __align__(128) __nv_bfloat16 g_wp[CH*CH];
__device__ float g_part[BATCH*NG][8][2];

// ---------------- helpers ----------------
__device__ __forceinline__ float warpSum(float v) {
    #pragma unroll
    for (int o = 16; o > 0; o >>= 1) v += __shfl_xor_sync(0xffffffffu, v, o);
    return v;
}
__device__ __forceinline__ uint32_t packbf(float a, float b) {
    __nv_bfloat162 h = __floats2bfloat162_rn(a, b);
    return *(uint32_t*)&h;
}
__device__ __forceinline__ uint32_t ex2h2(float lo, float hi) {
    uint32_t h;
    asm("cvt.rn.f16x2.f32 %0, %1, %2;" : "=r"(h) : "f"(hi), "f"(lo));
    asm("ex2.approx.f16x2 %0, %0;" : "+r"(h));
    return h;
}
__device__ __forceinline__ uint32_t hadd2u(uint32_t x, uint32_t y) {
    uint32_t d; asm("add.rn.f16x2 %0, %1, %2;" : "=r"(d) : "r"(x), "r"(y));
    return d;
}
__device__ __forceinline__ float2 h22f2(uint32_t h) {
    __half2 v = *(__half2*)&h;
    return __half22float2(v);
}
__device__ __forceinline__ void ldsm_x4(uint32_t& r0, uint32_t& r1,
                                        uint32_t& r2, uint32_t& r3, uint32_t addr) {
    asm volatile("ldmatrix.sync.aligned.m8n8.x4.shared.b16 {%0,%1,%2,%3}, [%4];"
                 : "=r"(r0), "=r"(r1), "=r"(r2), "=r"(r3) : "r"(addr));
}
__device__ __forceinline__ void ldsm_x4_t(uint32_t& r0, uint32_t& r1,
                                          uint32_t& r2, uint32_t& r3, uint32_t addr) {
    asm volatile("ldmatrix.sync.aligned.m8n8.x4.trans.shared.b16 {%0,%1,%2,%3}, [%4];"
                 : "=r"(r0), "=r"(r1), "=r"(r2), "=r"(r3) : "r"(addr));
}
__device__ __forceinline__ void cpasync16(uint32_t dst, const void* src) {
    asm volatile("cp.async.ca.shared.global [%0], [%1], 16;" :: "r"(dst), "l"(src) : "memory");
}
#define CP_COMMIT() asm volatile("cp.async.commit_group;" ::: "memory")
#define CP_WAIT0()  asm volatile("cp.async.wait_group 0;" ::: "memory")
#define CP_WAIT1()  asm volatile("cp.async.wait_group 1;" ::: "memory")
__device__ __forceinline__ void mma16816(float c[4], const uint32_t a[4],
                                         uint32_t b0, uint32_t b1) {
    asm volatile(
        "mma.sync.aligned.m16n8k16.row.col.f32.bf16.bf16.f32 "
        "{%0,%1,%2,%3}, {%4,%5,%6,%7}, {%8,%9}, {%0,%1,%2,%3};"
        : "+f"(c[0]), "+f"(c[1]), "+f"(c[2]), "+f"(c[3])
        : "r"(a[0]), "r"(a[1]), "r"(a[2]), "r"(a[3]), "r"(b0), "r"(b1));
}
__device__ __forceinline__ void mma16816h(float c[4], const uint32_t a[4],
                                          uint32_t b0, uint32_t b1) {
    asm volatile(
        "mma.sync.aligned.m16n8k16.row.col.f32.f16.f16.f32 "
        "{%0,%1,%2,%3}, {%4,%5,%6,%7}, {%8,%9}, {%0,%1,%2,%3};"
        : "+f"(c[0]), "+f"(c[1]), "+f"(c[2]), "+f"(c[3])
        : "r"(a[0]), "r"(a[1]), "r"(a[2]), "r"(a[3]), "r"(b0), "r"(b1));
}

// ---------------- 1a) GroupNorm partial reduce + weight convert ----------
__global__ void gn_reduce(const float* __restrict__ x,
                          const float* __restrict__ qw,
                          const float* __restrict__ pw) {
    if (blockIdx.x >= 128) {
        int i = (blockIdx.x - 128) * 256 + threadIdx.x;
        if (i < 196608) {
            float4 v = ((const float4*)qw)[i];
            uint2 p; p.x = packbf(v.x, v.y); p.y = packbf(v.z, v.w);
            *(uint2*)(g_wq + (size_t)i*4) = p;
        } else {
            int j = i - 196608;
            float4 v = ((const float4*)pw)[j];
            uint2 p; p.x = packbf(v.x, v.y); p.y = packbf(v.z, v.w);
            *(uint2*)(g_wp + (size_t)j*4) = p;
        }
        return;
    }
    int bg = blockIdx.x >> 3;
    int sl = blockIdx.x & 7;
    size_t base = (size_t)bg * CPG * HW + (size_t)sl * (CPG*HW/8);
    const float4* x4 = (const float4*)(x + base);
    const int NV = CPG*HW/8/4;

    float s = 0.f, s2 = 0.f;
    for (int i = threadIdx.x; i < NV; i += blockDim.x) {
        float4 t = x4[i];
        s  += t.x + t.y + t.z + t.w;
        s2 += t.x*t.x + t.y*t.y + t.z*t.z + t.w*t.w;
    }
    __shared__ float shs[8], shs2[8];
    s = warpSum(s); s2 = warpSum(s2);
    int wid = threadIdx.x >> 5, lane = threadIdx.x & 31;
    if (lane == 0) { shs[wid] = s; shs2[wid] = s2; }
    __syncthreads();
    if (threadIdx.x == 0) {
        float a = 0.f, c = 0.f;
        for (int i = 0; i < (int)(blockDim.x >> 5); i++) { a += shs[i]; c += shs2[i]; }
        g_part[bg][sl][0] = a;
        g_part[bg][sl][1] = c;
    }
}

// ---------------- 1b) GroupNorm apply, smem transpose -> [b][n][c] --------
__global__ __launch_bounds__(256) void gn_apply(const float* __restrict__ x,
                                                const float* __restrict__ w,
                                                const float* __restrict__ b) {
    __shared__ float tile[64][68];
    int bg = blockIdx.y;
    int bb = bg >> 3;
    int g  = bg & 7;
    float s = 0.f, s2 = 0.f;
    #pragma unroll
    for (int i = 0; i < 8; i++) { s += g_part[bg][i][0]; s2 += g_part[bg][i][1]; }
    const float invN = 1.f / (float)(CPG*HW);
    float mean = s * invN;
    float var  = s2 * invN - mean*mean;
    float rstd = rsqrtf(var + EPS);

    int n0 = blockIdx.x * 64;
    int tid = threadIdx.x;
    size_t base = (size_t)bg * CPG * HW;
    #pragma unroll
    for (int it = 0; it < 4; ++it) {
        int idx = tid + it*256;
        int r = idx >> 4, c = idx & 15;
        float4 v = *(const float4*)(x + base + (size_t)r*HW + n0 + c*4);
        int ch = g*CPG + r;
        float sc = w[ch] * rstd;
        float bo = b[ch] - mean * sc;
        float4 o;
        o.x = v.x*sc + bo; o.y = v.y*sc + bo;
        o.z = v.z*sc + bo; o.w = v.w*sc + bo;
        *(float4*)&tile[r][c*4] = o;
    }
    __syncthreads();
    int warp = tid >> 5, lane = tid & 31;
    __nv_bfloat16* outp = g_xn + (size_t)bb*HW*CH;
    #pragma unroll
    for (int rr = 0; rr < 8; ++rr) {
        int n = warp*8 + rr;
        float a0 = tile[lane*2][n], a1 = tile[lane*2+1][n];
        *(uint32_t*)(outp + (size_t)(n0+n)*CH + g*CPG + lane*2) = packbf(a0, a1);
    }
}

// ---------------- GEMM core: 3-stage ring, M-tile = 128*MR ----------------
#define GPAD 40
#define GSTG_B (128*GPAD*2)
template<int MR>
__device__ __forceinline__ void gcp_tileA(uint32_t dst, const __nv_bfloat16* src, int k0) {
    int tid = threadIdx.x;
    if (MR == 1) {
        int r = tid >> 1, hb = (tid & 1) * 32;
        const char* sp = (const char*)(src + (size_t)r*512 + k0);
        cpasync16(dst + r*80 + hb,      sp + hb);
        cpasync16(dst + r*80 + hb + 16, sp + hb + 16);
    } else {
        int r = tid;   // 256 rows, 64B each
        const char* sp = (const char*)(src + (size_t)r*512 + k0);
        cpasync16(dst + r*80,      sp);
        cpasync16(dst + r*80 + 16, sp + 16);
        cpasync16(dst + r*80 + 32, sp + 32);
        cpasync16(dst + r*80 + 48, sp + 48);
    }
}
__device__ __forceinline__ void gcp_tileB(uint32_t dst, const __nv_bfloat16* src, int k0) {
    int tid = threadIdx.x;
    int r = tid >> 1, hb = (tid & 1) * 32;
    const char* sp = (const char*)(src + (size_t)r*512 + k0);
    cpasync16(dst + r*80 + hb,      sp + hb);
    cpasync16(dst + r*80 + hb + 16, sp + hb + 16);
}

template<int MR>
__device__ __forceinline__ void gemm_core(const __nv_bfloat16* __restrict__ Ag,
                                          const __nv_bfloat16* __restrict__ Bg,
                                          char* As, char* Bs,
                                          float acc[4*MR][4][4]) {
    const int GSTG_A = 128*MR*GPAD*2;
    int tid = threadIdx.x;
    int warp = tid >> 5, lane = tid & 31;
    int wm = (warp >> 2) * 64 * MR, wn = (warp & 3) * 32;
    uint32_t as_b = (uint32_t)__cvta_generic_to_shared(As);
    uint32_t bs_b = (uint32_t)__cvta_generic_to_shared(Bs);
    int a_row = ((lane>>3)&1)*8 + (lane&7);
    int a_col = (lane>>4)*8;
    int b_row = ((lane>>4)&1)*8 + (lane&7);
    int b_col = ((lane>>3)&1)*8;

    gcp_tileA<MR>(as_b, Ag, 0);           gcp_tileB(bs_b, Bg, 0);           CP_COMMIT();
    gcp_tileA<MR>(as_b + GSTG_A, Ag, 32); gcp_tileB(bs_b + GSTG_B, Bg, 32); CP_COMMIT();

    int st = 0;
    for (int k0 = 0; k0 < 512; k0 += 32) {
        if (k0 == 480) { CP_WAIT0(); } else { CP_WAIT1(); }
        __syncthreads();
        if (k0 + 64 < 512) {
            int s2 = st + 2; if (s2 >= 3) s2 -= 3;
            gcp_tileA<MR>(as_b + s2*GSTG_A, Ag, k0 + 64);
            gcp_tileB(bs_b + s2*GSTG_B, Bg, k0 + 64);
            CP_COMMIT();
        }
        uint32_t ab = as_b + st*GSTG_A, bb = bs_b + st*GSTG_B;
        #pragma unroll
        for (int ks = 0; ks < 32; ks += 16) {
            uint32_t af[4*MR][4];
            #pragma unroll
            for (int mi = 0; mi < 4*MR; ++mi)
                ldsm_x4(af[mi][0], af[mi][1], af[mi][2], af[mi][3],
                        ab + ((wm + 16*mi + a_row)*GPAD + ks + a_col)*2);
            #pragma unroll
            for (int np = 0; np < 2; ++np) {
                uint32_t b00, b01, b10, b11;
                ldsm_x4(b00, b01, b10, b11,
                        bb + ((wn + 16*np + b_row)*GPAD + ks + b_col)*2);
                #pragma unroll
                for (int mi = 0; mi < 4*MR; ++mi) {
                    mma16816(acc[mi][2*np],   af[mi], b00, b01);
                    mma16816(acc[mi][2*np+1], af[mi], b10, b11);
                }
            }
        }
        st = st + 1; if (st >= 3) st = 0;
    }
}

// ---------------- 2) QKV GEMM, M-tile 256, coalesced [d][n] epilogue -----
__global__ __launch_bounds__(256) void gemm_qkv(const float* __restrict__ bias) {
    extern __shared__ char gsm[];
    char* As = gsm;                 // 3 * 256*80
    char* Bs = gsm + 3*(256*GPAD*2);
    int z = blockIdx.z;
    int m0 = blockIdx.y * 256, n0 = blockIdx.x * 128;
    float acc[8][4][4] = {};
    gemm_core<2>(g_wq + (size_t)m0*512, g_xn + (size_t)z*HW*CH + (size_t)n0*512,
                 As, Bs, acc);

    int warp = threadIdx.x >> 5, lane = threadIdx.x & 31;
    int g = lane >> 2, t = lane & 3;
    int wm = (warp >> 2) * 128, wn = (warp & 3) * 32;

    #pragma unroll
    for (int mi = 0; mi < 8; ++mi) {
        #pragma unroll
        for (int rr = 0; rr < 2; ++rr) {
            int o = m0 + wm + 16*mi + g + rr*8;
            float bi = bias[o];
            int h = (o >> 6) & 7, d = o & 63;
            size_t base = ((size_t)(z*NH + h)*HD + d)*HW;
            #pragma unroll
            for (int nj = 0; nj < 4; ++nj) {
                int n = n0 + wn + 8*nj + 2*t;
                float v0 = acc[mi][nj][rr*2 + 0] + bi;
                float v1 = acc[mi][nj][rr*2 + 1] + bi;
                if (o < 512) {
                    *(uint32_t*)&g_q[base + n] = packbf(v0*QSCALE, v1*QSCALE);
                } else if (o < 1024) {
                    *(uint32_t*)&g_k[base + n] = packbf(v0, v1);
                } else {
                    __half2 p = __floats2half2_rn(v0, v1);
                    *(uint32_t*)&g_v[base + n] = *(uint32_t*)&p;
                }
            }
        }
    }
}

// ---------------- 3) flash attention: R11 interleaved (best measured) ----
#define QPITCH 264
#define KVP    72
#define ASTG   (64*KVP*2)
__device__ __forceinline__ void kv_cp(uint32_t kd, uint32_t vd,
                                      const __nv_bfloat16* Kg, const __half* Vg,
                                      int m0k) {
    int t = threadIdx.x; int r = t >> 2, cb = (t & 3) * 32;
    const char* ks = (const char*)Kg + ((size_t)r*HW + m0k)*2;
    uint32_t kdst = kd + r*(KVP*2) + cb;
    cpasync16(kdst,      ks + cb);
    cpasync16(kdst + 16, ks + cb + 16);
    const char* vs = (const char*)Vg + ((size_t)r*HW + m0k)*2;
    uint32_t vdst = vd + r*(KVP*2) + cb;
    cpasync16(vdst,      vs + cb);
    cpasync16(vdst + 16, vs + cb + 16);
}

__global__ __launch_bounds__(256) void attn_kernel() {
    extern __shared__ char sm[];
    char* Qsm = sm;                               // [64 d][QPITCH n] bf16
    char* Ksm = sm + 64*QPITCH*2;                 // 2 stages
    char* Vsm = Ksm + 2*ASTG;                     // 2 stages
    uint32_t qs_b = (uint32_t)__cvta_generic_to_shared(Qsm);
    uint32_t ks_b = (uint32_t)__cvta_generic_to_shared(Ksm);
    uint32_t vs_b = (uint32_t)__cvta_generic_to_shared(Vsm);

    int bh = blockIdx.y, n0 = blockIdx.x * 256;
    const __nv_bfloat16* Qg = g_q + (size_t)bh*HD*HW;
    const __nv_bfloat16* Kg = g_k + (size_t)bh*HD*HW;
    const __half*        Vg = g_v + (size_t)bh*HD*HW;

    int tid = threadIdx.x, warp = tid >> 5, lane = tid & 31;
    int g = lane >> 2, t = lane & 3;
    int qrow = warp * 32;
    int aq_row = ((lane>>4)&1)*8 + (lane&7);
    int aq_col = ((lane>>3)&1)*8;
    int bk_row = ((lane>>3)&1)*8 + (lane&7);
    int bk_col = ((lane>>4)&1)*8;
    int bv_row = ((lane>>4)&1)*8 + (lane&7);
    int bv_col = ((lane>>3)&1)*8;

    kv_cp(ks_b, vs_b, Kg, Vg, 0);
    CP_COMMIT();

    {   // Q tile: 64 rows x 256 cols bf16
        int r = tid >> 2, c = (tid & 3) * 64;
        #pragma unroll
        for (int i = 0; i < 8; ++i)
            *(uint4*)(Qsm + ((size_t)r*QPITCH + c + i*8)*2) =
                *(const uint4*)(Qg + (size_t)r*HW + n0 + c + i*8);
    }
    __syncthreads();

    uint32_t qf[2][4][4];
    #pragma unroll
    for (int mi = 0; mi < 2; ++mi)
        #pragma unroll
        for (int ks = 0; ks < 4; ++ks)
            ldsm_x4_t(qf[mi][ks][0], qf[mi][ks][1], qf[mi][ks][2], qf[mi][ks][3],
                      qs_b + ((ks*16 + aq_row)*QPITCH + qrow + 16*mi + aq_col)*2);

    float o_acc[2][8][4] = {};
    float l_lo[2] = {0.f, 0.f}, l_hi[2] = {0.f, 0.f};

    for (int kb = 0; kb < 64; ++kb) {
        CP_WAIT0();
        __syncthreads();
        if (kb < 63) {
            int s2 = (kb + 1) & 1;
            kv_cp(ks_b + s2*ASTG, vs_b + s2*ASTG, Kg, Vg, (kb+1)*64);
            CP_COMMIT();
        }
        uint32_t kbb = ks_b + (kb & 1)*ASTG;
        uint32_t vbb = vs_b + (kb & 1)*ASTG;

        #pragma unroll
        for (int jp = 0; jp < 4; ++jp) {
            float s[2][2][4];
            #pragma unroll
            for (int mi = 0; mi < 2; ++mi)
                #pragma unroll
                for (int hh = 0; hh < 2; ++hh)
                    #pragma unroll
                    for (int i = 0; i < 4; ++i) s[mi][hh][i] = -MFIX;
            #pragma unroll
            for (int ks = 0; ks < 4; ++ks) {
                uint32_t b00, b01, b10, b11;
                ldsm_x4_t(b00, b01, b10, b11,
                          kbb + ((ks*16 + bk_row)*KVP + jp*16 + bk_col)*2);
                #pragma unroll
                for (int mi = 0; mi < 2; ++mi) {
                    mma16816(s[mi][0], qf[mi][ks], b00, b01);
                    mma16816(s[mi][1], qf[mi][ks], b10, b11);
                }
            }
            uint32_t pa[2][4];
            #pragma unroll
            for (int mi = 0; mi < 2; ++mi) {
                pa[mi][0] = ex2h2(s[mi][0][0], s[mi][0][1]);
                pa[mi][1] = ex2h2(s[mi][0][2], s[mi][0][3]);
                pa[mi][2] = ex2h2(s[mi][1][0], s[mi][1][1]);
                pa[mi][3] = ex2h2(s[mi][1][2], s[mi][1][3]);
                uint32_t rl = hadd2u(pa[mi][0], pa[mi][2]);
                uint32_t rh = hadd2u(pa[mi][1], pa[mi][3]);
                float2 fl = h22f2(rl), fh = h22f2(rh);
                l_lo[mi] += fl.x + fl.y;
                l_hi[mi] += fh.x + fh.y;
            }
            #pragma unroll
            for (int cp = 0; cp < 4; ++cp) {
                uint32_t v00, v01, v10, v11;
                ldsm_x4(v00, v01, v10, v11,
                        vbb + ((16*cp + bv_row)*KVP + jp*16 + bv_col)*2);
                #pragma unroll
                for (int mi = 0; mi < 2; ++mi) {
                    mma16816h(o_acc[mi][2*cp],   pa[mi], v00, v01);
                    mma16816h(o_acc[mi][2*cp+1], pa[mi], v10, v11);
                }
            }
        }
    }

    int b = bh >> 3, h = bh & 7;
    __nv_bfloat16* Og = g_o + (size_t)b*HW*CH;
    #pragma unroll
    for (int mi = 0; mi < 2; ++mi) {
        float ll = l_lo[mi], lh = l_hi[mi];
        ll += __shfl_xor_sync(0xffffffffu, ll, 1);
        ll += __shfl_xor_sync(0xffffffffu, ll, 2);
        lh += __shfl_xor_sync(0xffffffffu, lh, 1);
        lh += __shfl_xor_sync(0xffffffffu, lh, 2);
        float inv_lo = 1.f / ll, inv_hi = 1.f / lh;
        int r_lo = n0 + qrow + 16*mi + g, r_hi = r_lo + 8;
        #pragma unroll
        for (int c = 0; c < 8; ++c) {
            int col = h*64 + 8*c + 2*t;
            *(uint32_t*)(Og + (size_t)r_lo*CH + col) =
                packbf(o_acc[mi][c][0]*inv_lo, o_acc[mi][c][1]*inv_lo);
            *(uint32_t*)(Og + (size_t)r_hi*CH + col) =
                packbf(o_acc[mi][c][2]*inv_hi, o_acc[mi][c][3]*inv_hi);
        }
    }
}

// ---------------- 4) proj GEMM, M-tile 256 + bias + residual -------------
__global__ __launch_bounds__(256) void gemm_proj(const float* __restrict__ bias,
                                                 const float* __restrict__ x,
                                                 float* __restrict__ out) {
    extern __shared__ char gsm[];
    char* As = gsm;
    char* Bs = gsm + 3*(256*GPAD*2);
    int z = blockIdx.z;
    int m0 = blockIdx.y * 256, n0 = blockIdx.x * 128;
    float acc[8][4][4] = {};
    gemm_core<2>(g_wp + (size_t)m0*512, g_o + (size_t)z*HW*CH + (size_t)n0*512,
                 As, Bs, acc);

    int warp = threadIdx.x >> 5, lane = threadIdx.x & 31;
    int g = lane >> 2, t = lane & 3;
    int wm = (warp >> 2) * 128, wn = (warp & 3) * 32;

    #pragma unroll
    for (int mi = 0; mi < 8; ++mi) {
        #pragma unroll
        for (int rr = 0; rr < 2; ++rr) {
            int c = m0 + wm + 16*mi + g + rr*8;
            float bi = bias[c];
            size_t rowb = ((size_t)z*CH + c)*HW;
            #pragma unroll
            for (int nj = 0; nj < 4; ++nj) {
                int n = n0 + wn + 8*nj + 2*t;
                float2 xr = *(const float2*)(x + rowb + n);
                float2 o;
                o.x = acc[mi][nj][rr*2 + 0] + bi + xr.x;
                o.y = acc[mi][nj][rr*2 + 1] + bi + xr.y;
                *(float2*)(out + rowb + n) = o;
            }
        }
    }
}

// ---------------- launch ----------------
extern "C" void kernel_launch(void* const* d_in, const int* in_sizes, int n_in,
                              void* d_out, int out_size) {
    const float* x      = (const float*)d_in[0];
    const float* norm_w = (const float*)d_in[1];
    const float* norm_b = (const float*)d_in[2];
    const float* qkv_w  = (const float*)d_in[3];
    const float* qkv_b  = (const float*)d_in[4];
    const float* proj_w = (const float*)d_in[5];
    const float* proj_b = (const float*)d_in[6];
    float* out = (float*)d_out;

    const int ASMEM = 64*QPITCH*2 + 4*ASTG;                 // 70656
    const int GSMEM = 3*(256*GPAD*2) + 3*GSTG_B;            // 61440 + 30720 = 92160
    cudaFuncSetAttribute(attn_kernel,
                         cudaFuncAttributeMaxDynamicSharedMemorySize, ASMEM);
    cudaFuncSetAttribute(gemm_qkv,
                         cudaFuncAttributeMaxDynamicSharedMemorySize, GSMEM);
    cudaFuncSetAttribute(gemm_proj,
                         cudaFuncAttributeMaxDynamicSharedMemorySize, GSMEM);

    gn_reduce<<<128 + 1024, 256>>>(x, qkv_w, proj_w);
    gn_apply<<<dim3(HW/64, BATCH*NG), 256>>>(x, norm_w, norm_b);
    gemm_qkv<<<dim3(HW/128, 6, BATCH), 256, GSMEM>>>(qkv_b);
    attn_kernel<<<dim3(HW/256, BATCH*NH), 256, ASMEM>>>();
    gemm_proj<<<dim3(HW/128, 2, BATCH), 256, GSMEM>>>(proj_b, x, out);
}

// round 15
// speedup vs baseline: 1.0430x; 1.0430x over previous
#include <cuda_runtime.h>
#include <cuda_bf16.h>
#include <cuda_fp16.h>
#include <math.h>
#include <stdint.h>

#define BATCH 2
#define CH    512
#define NH    8
#define HD    64
#define HW    4096
#define NG    8
#define CPG   64
#define EPS   1e-5f
#define LOG2E 1.4426950408889634f
#define QSCALE (0.125f * LOG2E)
#define MFIX  8.0f

// ---------------- scratch ----------------
__device__ __align__(128) __nv_bfloat16 g_xn[(size_t)BATCH*HW*CH];   // [b][n][c]
__device__ __align__(128) __nv_bfloat16 g_q[(size_t)BATCH*NH*HD*HW]; // [bh][d][n] scaled
__device__ __align__(128) __nv_bfloat16 g_k[(size_t)BATCH*NH*HD*HW]; // [bh][d][n]
__device__ __align__(128) __half        g_v[(size_t)BATCH*NH*HD*HW]; // [bh][d][n] fp16
__device__ __align__(128) __nv_bfloat16 g_o[(size_t)BATCH*HW*CH];    // [b][n][c]
__device__ __align__(128) __nv_bfloat16 g_wq[3*CH*CH];
__device__ __align__(128) __nv_bfloat16 g_wp[CH*CH];
__device__ float g_part[BATCH*NG][8][2];

// ---------------- helpers ----------------
__device__ __forceinline__ float warpSum(float v) {
    #pragma unroll
    for (int o = 16; o > 0; o >>= 1) v += __shfl_xor_sync(0xffffffffu, v, o);
    return v;
}
__device__ __forceinline__ uint32_t packbf(float a, float b) {
    __nv_bfloat162 h = __floats2bfloat162_rn(a, b);
    return *(uint32_t*)&h;
}
__device__ __forceinline__ uint32_t ex2h2(float lo, float hi) {
    uint32_t h;
    asm("cvt.rn.f16x2.f32 %0, %1, %2;" : "=r"(h) : "f"(hi), "f"(lo));
    asm("ex2.approx.f16x2 %0, %0;" : "+r"(h));
    return h;
}
__device__ __forceinline__ uint32_t hadd2u(uint32_t x, uint32_t y) {
    uint32_t d; asm("add.rn.f16x2 %0, %1, %2;" : "=r"(d) : "r"(x), "r"(y));
    return d;
}
__device__ __forceinline__ float2 h22f2(uint32_t h) {
    __half2 v = *(__half2*)&h;
    return __half22float2(v);
}
__device__ __forceinline__ void ldsm_x4(uint32_t& r0, uint32_t& r1,
                                        uint32_t& r2, uint32_t& r3, uint32_t addr) {
    asm volatile("ldmatrix.sync.aligned.m8n8.x4.shared.b16 {%0,%1,%2,%3}, [%4];"
                 : "=r"(r0), "=r"(r1), "=r"(r2), "=r"(r3) : "r"(addr));
}
__device__ __forceinline__ void ldsm_x4_t(uint32_t& r0, uint32_t& r1,
                                          uint32_t& r2, uint32_t& r3, uint32_t addr) {
    asm volatile("ldmatrix.sync.aligned.m8n8.x4.trans.shared.b16 {%0,%1,%2,%3}, [%4];"
                 : "=r"(r0), "=r"(r1), "=r"(r2), "=r"(r3) : "r"(addr));
}
__device__ __forceinline__ void cpasync16(uint32_t dst, const void* src) {
    asm volatile("cp.async.ca.shared.global [%0], [%1], 16;" :: "r"(dst), "l"(src) : "memory");
}
#define CP_COMMIT() asm volatile("cp.async.commit_group;" ::: "memory")
#define CP_WAIT0()  asm volatile("cp.async.wait_group 0;" ::: "memory")
#define CP_WAIT1()  asm volatile("cp.async.wait_group 1;" ::: "memory")
#define CP_WAIT2()  asm volatile("cp.async.wait_group 2;" ::: "memory")
__device__ __forceinline__ void mma16816(float c[4], const uint32_t a[4],
                                         uint32_t b0, uint32_t b1) {
    asm volatile(
        "mma.sync.aligned.m16n8k16.row.col.f32.bf16.bf16.f32 "
        "{%0,%1,%2,%3}, {%4,%5,%6,%7}, {%8,%9}, {%0,%1,%2,%3};"
        : "+f"(c[0]), "+f"(c[1]), "+f"(c[2]), "+f"(c[3])
        : "r"(a[0]), "r"(a[1]), "r"(a[2]), "r"(a[3]), "r"(b0), "r"(b1));
}
__device__ __forceinline__ void mma16816h(float c[4], const uint32_t a[4],
                                          uint32_t b0, uint32_t b1) {
    asm volatile(
        "mma.sync.aligned.m16n8k16.row.col.f32.f16.f16.f32 "
        "{%0,%1,%2,%3}, {%4,%5,%6,%7}, {%8,%9}, {%0,%1,%2,%3};"
        : "+f"(c[0]), "+f"(c[1]), "+f"(c[2]), "+f"(c[3])
        : "r"(a[0]), "r"(a[1]), "r"(a[2]), "r"(a[3]), "r"(b0), "r"(b1));
}

// ---------------- 1a) GroupNorm partial reduce + weight convert ----------
__global__ void gn_reduce(const float* __restrict__ x,
                          const float* __restrict__ qw,
                          const float* __restrict__ pw) {
    if (blockIdx.x >= 128) {
        int i = (blockIdx.x - 128) * 256 + threadIdx.x;
        if (i < 196608) {
            float4 v = ((const float4*)qw)[i];
            uint2 p; p.x = packbf(v.x, v.y); p.y = packbf(v.z, v.w);
            *(uint2*)(g_wq + (size_t)i*4) = p;
        } else {
            int j = i - 196608;
            float4 v = ((const float4*)pw)[j];
            uint2 p; p.x = packbf(v.x, v.y); p.y = packbf(v.z, v.w);
            *(uint2*)(g_wp + (size_t)j*4) = p;
        }
        return;
    }
    int bg = blockIdx.x >> 3;
    int sl = blockIdx.x & 7;
    size_t base = (size_t)bg * CPG * HW + (size_t)sl * (CPG*HW/8);
    const float4* x4 = (const float4*)(x + base);
    const int NV = CPG*HW/8/4;

    float s = 0.f, s2 = 0.f;
    for (int i = threadIdx.x; i < NV; i += blockDim.x) {
        float4 t = x4[i];
        s  += t.x + t.y + t.z + t.w;
        s2 += t.x*t.x + t.y*t.y + t.z*t.z + t.w*t.w;
    }
    __shared__ float shs[8], shs2[8];
    s = warpSum(s); s2 = warpSum(s2);
    int wid = threadIdx.x >> 5, lane = threadIdx.x & 31;
    if (lane == 0) { shs[wid] = s; shs2[wid] = s2; }
    __syncthreads();
    if (threadIdx.x == 0) {
        float a = 0.f, c = 0.f;
        for (int i = 0; i < (int)(blockDim.x >> 5); i++) { a += shs[i]; c += shs2[i]; }
        g_part[bg][sl][0] = a;
        g_part[bg][sl][1] = c;
    }
}

// ---------------- 1b) GroupNorm apply, smem transpose -> [b][n][c] --------
__global__ __launch_bounds__(256) void gn_apply(const float* __restrict__ x,
                                                const float* __restrict__ w,
                                                const float* __restrict__ b) {
    __shared__ float tile[64][68];
    int bg = blockIdx.y;
    int bb = bg >> 3;
    int g  = bg & 7;
    float s = 0.f, s2 = 0.f;
    #pragma unroll
    for (int i = 0; i < 8; i++) { s += g_part[bg][i][0]; s2 += g_part[bg][i][1]; }
    const float invN = 1.f / (float)(CPG*HW);
    float mean = s * invN;
    float var  = s2 * invN - mean*mean;
    float rstd = rsqrtf(var + EPS);

    int n0 = blockIdx.x * 64;
    int tid = threadIdx.x;
    size_t base = (size_t)bg * CPG * HW;
    #pragma unroll
    for (int it = 0; it < 4; ++it) {
        int idx = tid + it*256;
        int r = idx >> 4, c = idx & 15;
        float4 v = *(const float4*)(x + base + (size_t)r*HW + n0 + c*4);
        int ch = g*CPG + r;
        float sc = w[ch] * rstd;
        float bo = b[ch] - mean * sc;
        float4 o;
        o.x = v.x*sc + bo; o.y = v.y*sc + bo;
        o.z = v.z*sc + bo; o.w = v.w*sc + bo;
        *(float4*)&tile[r][c*4] = o;
    }
    __syncthreads();
    int warp = tid >> 5, lane = tid & 31;
    __nv_bfloat16* outp = g_xn + (size_t)bb*HW*CH;
    #pragma unroll
    for (int rr = 0; rr < 8; ++rr) {
        int n = warp*8 + rr;
        float a0 = tile[lane*2][n], a1 = tile[lane*2+1][n];
        *(uint32_t*)(outp + (size_t)(n0+n)*CH + g*CPG + lane*2) = packbf(a0, a1);
    }
}

// ---------------- GEMM core: 4-stage cp.async ring ----------------
#define GPAD 40
#define GSTG (128*GPAD*2)
__device__ __forceinline__ void gcp_tile(uint32_t dst, const __nv_bfloat16* src, int k0) {
    int tid = threadIdx.x;
    int r = tid >> 1, hb = (tid & 1) * 32;
    const char* sp = (const char*)(src + (size_t)r*512 + k0);
    cpasync16(dst + r*80 + hb,      sp + hb);
    cpasync16(dst + r*80 + hb + 16, sp + hb + 16);
}

__device__ __forceinline__ void gemm_core(const __nv_bfloat16* __restrict__ Ag,
                                          const __nv_bfloat16* __restrict__ Bg,
                                          char* As, char* Bs,
                                          float acc[4][4][4]) {
    int tid = threadIdx.x;
    int warp = tid >> 5, lane = tid & 31;
    int wm = (warp >> 2) * 64, wn = (warp & 3) * 32;
    uint32_t as_b = (uint32_t)__cvta_generic_to_shared(As);
    uint32_t bs_b = (uint32_t)__cvta_generic_to_shared(Bs);
    int a_row = ((lane>>3)&1)*8 + (lane&7);
    int a_col = (lane>>4)*8;
    int b_row = ((lane>>4)&1)*8 + (lane&7);
    int b_col = ((lane>>3)&1)*8;

    gcp_tile(as_b,          Ag, 0);  gcp_tile(bs_b,          Bg, 0);  CP_COMMIT();
    gcp_tile(as_b + GSTG,   Ag, 32); gcp_tile(bs_b + GSTG,   Bg, 32); CP_COMMIT();
    gcp_tile(as_b + 2*GSTG, Ag, 64); gcp_tile(bs_b + 2*GSTG, Bg, 64); CP_COMMIT();

    int st = 0;
    for (int k0 = 0; k0 < 512; k0 += 32) {
        if (k0 <= 416)      { CP_WAIT2(); }
        else if (k0 == 448) { CP_WAIT1(); }
        else                { CP_WAIT0(); }
        __syncthreads();          // stage st ready; all warps done with stage (st+3)&3
        if (k0 + 96 < 512) {
            int s2 = (st + 3) & 3;
            gcp_tile(as_b + s2*GSTG, Ag, k0 + 96);
            gcp_tile(bs_b + s2*GSTG, Bg, k0 + 96);
            CP_COMMIT();
        }
        uint32_t ab = as_b + st*GSTG, bb = bs_b + st*GSTG;
        #pragma unroll
        for (int ks = 0; ks < 32; ks += 16) {
            uint32_t af[4][4];
            #pragma unroll
            for (int mi = 0; mi < 4; ++mi)
                ldsm_x4(af[mi][0], af[mi][1], af[mi][2], af[mi][3],
                        ab + ((wm + 16*mi + a_row)*GPAD + ks + a_col)*2);
            #pragma unroll
            for (int np = 0; np < 2; ++np) {
                uint32_t b00, b01, b10, b11;
                ldsm_x4(b00, b01, b10, b11,
                        bb + ((wn + 16*np + b_row)*GPAD + ks + b_col)*2);
                #pragma unroll
                for (int mi = 0; mi < 4; ++mi) {
                    mma16816(acc[mi][2*np],   af[mi], b00, b01);
                    mma16816(acc[mi][2*np+1], af[mi], b10, b11);
                }
            }
        }
        st = (st + 1) & 3;
    }
}

// ---------------- 2) QKV GEMM, coalesced [d][n] epilogue ----------------
__global__ __launch_bounds__(256) void gemm_qkv(const float* __restrict__ bias) {
    extern __shared__ char gsm[];
    char* As = gsm;
    char* Bs = gsm + 4*GSTG;
    int z = blockIdx.z;
    int m0 = blockIdx.x * 128, n0 = blockIdx.y * 128;   // m fastest: B-tile L2 locality
    float acc[4][4][4] = {};
    gemm_core(g_wq + (size_t)m0*512, g_xn + (size_t)z*HW*CH + (size_t)n0*512,
              As, Bs, acc);

    int warp = threadIdx.x >> 5, lane = threadIdx.x & 31;
    int g = lane >> 2, t = lane & 3;
    int wm = (warp >> 2) * 64, wn = (warp & 3) * 32;

    #pragma unroll
    for (int mi = 0; mi < 4; ++mi) {
        #pragma unroll
        for (int rr = 0; rr < 2; ++rr) {
            int o = m0 + wm + 16*mi + g + rr*8;
            float bi = bias[o];
            int h = (o >> 6) & 7, d = o & 63;
            size_t base = ((size_t)(z*NH + h)*HD + d)*HW;
            #pragma unroll
            for (int nj = 0; nj < 4; ++nj) {
                int n = n0 + wn + 8*nj + 2*t;
                float v0 = acc[mi][nj][rr*2 + 0] + bi;
                float v1 = acc[mi][nj][rr*2 + 1] + bi;
                if (o < 512) {
                    *(uint32_t*)&g_q[base + n] = packbf(v0*QSCALE, v1*QSCALE);
                } else if (o < 1024) {
                    *(uint32_t*)&g_k[base + n] = packbf(v0, v1);
                } else {
                    __half2 p = __floats2half2_rn(v0, v1);
                    *(uint32_t*)&g_v[base + n] = *(uint32_t*)&p;
                }
            }
        }
    }
}

// ---------------- 3) flash attention: R11 interleaved (best measured) ----
#define QPITCH 264
#define KVP    72
#define ASTG   (64*KVP*2)
__device__ __forceinline__ void kv_cp(uint32_t kd, uint32_t vd,
                                      const __nv_bfloat16* Kg, const __half* Vg,
                                      int m0k) {
    int t = threadIdx.x; int r = t >> 2, cb = (t & 3) * 32;
    const char* ks = (const char*)Kg + ((size_t)r*HW + m0k)*2;
    uint32_t kdst = kd + r*(KVP*2) + cb;
    cpasync16(kdst,      ks + cb);
    cpasync16(kdst + 16, ks + cb + 16);
    const char* vs = (const char*)Vg + ((size_t)r*HW + m0k)*2;
    uint32_t vdst = vd + r*(KVP*2) + cb;
    cpasync16(vdst,      vs + cb);
    cpasync16(vdst + 16, vs + cb + 16);
}

__global__ __launch_bounds__(256) void attn_kernel() {
    extern __shared__ char sm[];
    char* Qsm = sm;                               // [64 d][QPITCH n] bf16
    char* Ksm = sm + 64*QPITCH*2;                 // 2 stages
    char* Vsm = Ksm + 2*ASTG;                     // 2 stages
    uint32_t qs_b = (uint32_t)__cvta_generic_to_shared(Qsm);
    uint32_t ks_b = (uint32_t)__cvta_generic_to_shared(Ksm);
    uint32_t vs_b = (uint32_t)__cvta_generic_to_shared(Vsm);

    int bh = blockIdx.y, n0 = blockIdx.x * 256;
    const __nv_bfloat16* Qg = g_q + (size_t)bh*HD*HW;
    const __nv_bfloat16* Kg = g_k + (size_t)bh*HD*HW;
    const __half*        Vg = g_v + (size_t)bh*HD*HW;

    int tid = threadIdx.x, warp = tid >> 5, lane = tid & 31;
    int g = lane >> 2, t = lane & 3;
    int qrow = warp * 32;
    int aq_row = ((lane>>4)&1)*8 + (lane&7);
    int aq_col = ((lane>>3)&1)*8;
    int bk_row = ((lane>>3)&1)*8 + (lane&7);
    int bk_col = ((lane>>4)&1)*8;
    int bv_row = ((lane>>4)&1)*8 + (lane&7);
    int bv_col = ((lane>>3)&1)*8;

    kv_cp(ks_b, vs_b, Kg, Vg, 0);
    CP_COMMIT();

    {   // Q tile: 64 rows x 256 cols bf16
        int r = tid >> 2, c = (tid & 3) * 64;
        #pragma unroll
        for (int i = 0; i < 8; ++i)
            *(uint4*)(Qsm + ((size_t)r*QPITCH + c + i*8)*2) =
                *(const uint4*)(Qg + (size_t)r*HW + n0 + c + i*8);
    }
    __syncthreads();

    uint32_t qf[2][4][4];
    #pragma unroll
    for (int mi = 0; mi < 2; ++mi)
        #pragma unroll
        for (int ks = 0; ks < 4; ++ks)
            ldsm_x4_t(qf[mi][ks][0], qf[mi][ks][1], qf[mi][ks][2], qf[mi][ks][3],
                      qs_b + ((ks*16 + aq_row)*QPITCH + qrow + 16*mi + aq_col)*2);

    float o_acc[2][8][4] = {};
    float l_lo[2] = {0.f, 0.f}, l_hi[2] = {0.f, 0.f};

    for (int kb = 0; kb < 64; ++kb) {
        CP_WAIT0();
        __syncthreads();
        if (kb < 63) {
            int s2 = (kb + 1) & 1;
            kv_cp(ks_b + s2*ASTG, vs_b + s2*ASTG, Kg, Vg, (kb+1)*64);
            CP_COMMIT();
        }
        uint32_t kbb = ks_b + (kb & 1)*ASTG;
        uint32_t vbb = vs_b + (kb & 1)*ASTG;

        #pragma unroll
        for (int jp = 0; jp < 4; ++jp) {
            float s[2][2][4];
            #pragma unroll
            for (int mi = 0; mi < 2; ++mi)
                #pragma unroll
                for (int hh = 0; hh < 2; ++hh)
                    #pragma unroll
                    for (int i = 0; i < 4; ++i) s[mi][hh][i] = -MFIX;
            #pragma unroll
            for (int ks = 0; ks < 4; ++ks) {
                uint32_t b00, b01, b10, b11;
                ldsm_x4_t(b00, b01, b10, b11,
                          kbb + ((ks*16 + bk_row)*KVP + jp*16 + bk_col)*2);
                #pragma unroll
                for (int mi = 0; mi < 2; ++mi) {
                    mma16816(s[mi][0], qf[mi][ks], b00, b01);
                    mma16816(s[mi][1], qf[mi][ks], b10, b11);
                }
            }
            uint32_t pa[2][4];
            #pragma unroll
            for (int mi = 0; mi < 2; ++mi) {
                pa[mi][0] = ex2h2(s[mi][0][0], s[mi][0][1]);
                pa[mi][1] = ex2h2(s[mi][0][2], s[mi][0][3]);
                pa[mi][2] = ex2h2(s[mi][1][0], s[mi][1][1]);
                pa[mi][3] = ex2h2(s[mi][1][2], s[mi][1][3]);
                uint32_t rl = hadd2u(pa[mi][0], pa[mi][2]);
                uint32_t rh = hadd2u(pa[mi][1], pa[mi][3]);
                float2 fl = h22f2(rl), fh = h22f2(rh);
                l_lo[mi] += fl.x + fl.y;
                l_hi[mi] += fh.x + fh.y;
            }
            #pragma unroll
            for (int cp = 0; cp < 4; ++cp) {
                uint32_t v00, v01, v10, v11;
                ldsm_x4(v00, v01, v10, v11,
                        vbb + ((16*cp + bv_row)*KVP + jp*16 + bv_col)*2);
                #pragma unroll
                for (int mi = 0; mi < 2; ++mi) {
                    mma16816h(o_acc[mi][2*cp],   pa[mi], v00, v01);
                    mma16816h(o_acc[mi][2*cp+1], pa[mi], v10, v11);
                }
            }
        }
    }

    int b = bh >> 3, h = bh & 7;
    __nv_bfloat16* Og = g_o + (size_t)b*HW*CH;
    #pragma unroll
    for (int mi = 0; mi < 2; ++mi) {
        float ll = l_lo[mi], lh = l_hi[mi];
        ll += __shfl_xor_sync(0xffffffffu, ll, 1);
        ll += __shfl_xor_sync(0xffffffffu, ll, 2);
        lh += __shfl_xor_sync(0xffffffffu, lh, 1);
        lh += __shfl_xor_sync(0xffffffffu, lh, 2);
        float inv_lo = 1.f / ll, inv_hi = 1.f / lh;
        int r_lo = n0 + qrow + 16*mi + g, r_hi = r_lo + 8;
        #pragma unroll
        for (int c = 0; c < 8; ++c) {
            int col = h*64 + 8*c + 2*t;
            *(uint32_t*)(Og + (size_t)r_lo*CH + col) =
                packbf(o_acc[mi][c][0]*inv_lo, o_acc[mi][c][1]*inv_lo);
            *(uint32_t*)(Og + (size_t)r_hi*CH + col) =
                packbf(o_acc[mi][c][2]*inv_hi, o_acc[mi][c][3]*inv_hi);
        }
    }
}

// ---------------- 4) proj GEMM + bias + residual ----------------
__global__ __launch_bounds__(256) void gemm_proj(const float* __restrict__ bias,
                                                 const float* __restrict__ x,
                                                 float* __restrict__ out) {
    extern __shared__ char gsm[];
    char* As = gsm;
    char* Bs = gsm + 4*GSTG;
    int z = blockIdx.z;
    int m0 = blockIdx.x * 128, n0 = blockIdx.y * 128;   // m fastest
    float acc[4][4][4] = {};
    gemm_core(g_wp + (size_t)m0*512, g_o + (size_t)z*HW*CH + (size_t)n0*512,
              As, Bs, acc);

    int warp = threadIdx.x >> 5, lane = threadIdx.x & 31;
    int g = lane >> 2, t = lane & 3;
    int wm = (warp >> 2) * 64, wn = (warp & 3) * 32;

    #pragma unroll
    for (int mi = 0; mi < 4; ++mi) {
        #pragma unroll
        for (int rr = 0; rr < 2; ++rr) {
            int c = m0 + wm + 16*mi + g + rr*8;
            float bi = bias[c];
            size_t rowb = ((size_t)z*CH + c)*HW;
            #pragma unroll
            for (int nj = 0; nj < 4; ++nj) {
                int n = n0 + wn + 8*nj + 2*t;
                float2 xr = *(const float2*)(x + rowb + n);
                float2 o;
                o.x = acc[mi][nj][rr*2 + 0] + bi + xr.x;
                o.y = acc[mi][nj][rr*2 + 1] + bi + xr.y;
                *(float2*)(out + rowb + n) = o;
            }
        }
    }
}

// ---------------- launch ----------------
extern "C" void kernel_launch(void* const* d_in, const int* in_sizes, int n_in,
                              void* d_out, int out_size) {
    const float* x      = (const float*)d_in[0];
    const float* norm_w = (const float*)d_in[1];
    const float* norm_b = (const float*)d_in[2];
    const float* qkv_w  = (const float*)d_in[3];
    const float* qkv_b  = (const float*)d_in[4];
    const float* proj_w = (const float*)d_in[5];
    const float* proj_b = (const float*)d_in[6];
    float* out = (float*)d_out;

    const int ASMEM = 64*QPITCH*2 + 4*ASTG;   // 70656
    const int GSMEM = 8*GSTG;                  // 81920
    cudaFuncSetAttribute(attn_kernel,
                         cudaFuncAttributeMaxDynamicSharedMemorySize, ASMEM);
    cudaFuncSetAttribute(gemm_qkv,
                         cudaFuncAttributeMaxDynamicSharedMemorySize, GSMEM);
    cudaFuncSetAttribute(gemm_proj,
                         cudaFuncAttributeMaxDynamicSharedMemorySize, GSMEM);

    gn_reduce<<<128 + 1024, 256>>>(x, qkv_w, proj_w);
    gn_apply<<<dim3(HW/64, BATCH*NG), 256>>>(x, norm_w, norm_b);
    gemm_qkv<<<dim3(12, HW/128, BATCH), 256, GSMEM>>>(qkv_b);
    attn_kernel<<<dim3(HW/256, BATCH*NH), 256, ASMEM>>>();
    gemm_proj<<<dim3(4, HW/128, BATCH), 256, GSMEM>>>(proj_b, x, out);
}

// round 16
// speedup vs baseline: 1.1202x; 1.0740x over previous
#include <cuda_runtime.h>
#include <cuda_bf16.h>
#include <cuda_fp16.h>
#include <math.h>
#include <stdint.h>

#define BATCH 2
#define CH    512
#define NH    8
#define HD    64
#define HW    4096
#define NG    8
#define CPG   64
#define EPS   1e-5f
#define LOG2E 1.4426950408889634f
#define QSCALE (0.125f * LOG2E)
#define MFIX  8.0f

// ---------------- scratch ----------------
__device__ __align__(128) __nv_bfloat16 g_xn[(size_t)BATCH*HW*CH];   // [b][n][c]
__device__ __align__(128) __nv_bfloat16 g_q[(size_t)BATCH*NH*HD*HW]; // [bh][d][n] scaled
__device__ __align__(128) __nv_bfloat16 g_k[(size_t)BATCH*NH*HD*HW]; // [bh][d][n]
__device__ __align__(128) __half        g_v[(size_t)BATCH*NH*HD*HW]; // [bh][d][n] fp16
__device__ __align__(128) __nv_bfloat16 g_o[(size_t)BATCH*HW*CH];    // [b][n][c]
__device__ __align__(128) __nv_bfloat16 g_wq[3*CH*CH];
__device__ __align__(128) __nv_bfloat16 g_wp[CH*CH];
__device__ float g_part[BATCH*NG][8][2];

// ---------------- helpers ----------------
__device__ __forceinline__ float warpSum(float v) {
    #pragma unroll
    for (int o = 16; o > 0; o >>= 1) v += __shfl_xor_sync(0xffffffffu, v, o);
    return v;
}
__device__ __forceinline__ uint32_t packbf(float a, float b) {
    __nv_bfloat162 h = __floats2bfloat162_rn(a, b);
    return *(uint32_t*)&h;
}
__device__ __forceinline__ uint32_t ex2h2(float lo, float hi) {
    uint32_t h;
    asm("cvt.rn.f16x2.f32 %0, %1, %2;" : "=r"(h) : "f"(hi), "f"(lo));
    asm("ex2.approx.f16x2 %0, %0;" : "+r"(h));
    return h;
}
__device__ __forceinline__ uint32_t hadd2u(uint32_t x, uint32_t y) {
    uint32_t d; asm("add.rn.f16x2 %0, %1, %2;" : "=r"(d) : "r"(x), "r"(y));
    return d;
}
__device__ __forceinline__ float2 h22f2(uint32_t h) {
    __half2 v = *(__half2*)&h;
    return __half22float2(v);
}
__device__ __forceinline__ void ldsm_x4(uint32_t& r0, uint32_t& r1,
                                        uint32_t& r2, uint32_t& r3, uint32_t addr) {
    asm volatile("ldmatrix.sync.aligned.m8n8.x4.shared.b16 {%0,%1,%2,%3}, [%4];"
                 : "=r"(r0), "=r"(r1), "=r"(r2), "=r"(r3) : "r"(addr));
}
__device__ __forceinline__ void ldsm_x4_t(uint32_t& r0, uint32_t& r1,
                                          uint32_t& r2, uint32_t& r3, uint32_t addr) {
    asm volatile("ldmatrix.sync.aligned.m8n8.x4.trans.shared.b16 {%0,%1,%2,%3}, [%4];"
                 : "=r"(r0), "=r"(r1), "=r"(r2), "=r"(r3) : "r"(addr));
}
__device__ __forceinline__ void cpasync16(uint32_t dst, const void* src) {
    asm volatile("cp.async.ca.shared.global [%0], [%1], 16;" :: "r"(dst), "l"(src) : "memory");
}
#define CP_COMMIT() asm volatile("cp.async.commit_group;" ::: "memory")
#define CP_WAIT0()  asm volatile("cp.async.wait_group 0;" ::: "memory")
#define CP_WAIT1()  asm volatile("cp.async.wait_group 1;" ::: "memory")
__device__ __forceinline__ void mma16816(float c[4], const uint32_t a[4],
                                         uint32_t b0, uint32_t b1) {
    asm volatile(
        "mma.sync.aligned.m16n8k16.row.col.f32.bf16.bf16.f32 "
        "{%0,%1,%2,%3}, {%4,%5,%6,%7}, {%8,%9}, {%0,%1,%2,%3};"
        : "+f"(c[0]), "+f"(c[1]), "+f"(c[2]), "+f"(c[3])
        : "r"(a[0]), "r"(a[1]), "r"(a[2]), "r"(a[3]), "r"(b0), "r"(b1));
}
__device__ __forceinline__ void mma16816h(float c[4], const uint32_t a[4],
                                          uint32_t b0, uint32_t b1) {
    asm volatile(
        "mma.sync.aligned.m16n8k16.row.col.f32.f16.f16.f32 "
        "{%0,%1,%2,%3}, {%4,%5,%6,%7}, {%8,%9}, {%0,%1,%2,%3};"
        : "+f"(c[0]), "+f"(c[1]), "+f"(c[2]), "+f"(c[3])
        : "r"(a[0]), "r"(a[1]), "r"(a[2]), "r"(a[3]), "r"(b0), "r"(b1));
}

// ---------------- 1a) GroupNorm partial reduce + weight convert (both b) --
__global__ void gn_reduce(const float* __restrict__ x,
                          const float* __restrict__ qw,
                          const float* __restrict__ pw) {
    if (blockIdx.x >= 128) {
        int i = (blockIdx.x - 128) * 256 + threadIdx.x;
        if (i < 196608) {
            float4 v = ((const float4*)qw)[i];
            uint2 p; p.x = packbf(v.x, v.y); p.y = packbf(v.z, v.w);
            *(uint2*)(g_wq + (size_t)i*4) = p;
        } else {
            int j = i - 196608;
            float4 v = ((const float4*)pw)[j];
            uint2 p; p.x = packbf(v.x, v.y); p.y = packbf(v.z, v.w);
            *(uint2*)(g_wp + (size_t)j*4) = p;
        }
        return;
    }
    int bg = blockIdx.x >> 3;
    int sl = blockIdx.x & 7;
    size_t base = (size_t)bg * CPG * HW + (size_t)sl * (CPG*HW/8);
    const float4* x4 = (const float4*)(x + base);
    const int NV = CPG*HW/8/4;

    float s = 0.f, s2 = 0.f;
    for (int i = threadIdx.x; i < NV; i += blockDim.x) {
        float4 t = x4[i];
        s  += t.x + t.y + t.z + t.w;
        s2 += t.x*t.x + t.y*t.y + t.z*t.z + t.w*t.w;
    }
    __shared__ float shs[8], shs2[8];
    s = warpSum(s); s2 = warpSum(s2);
    int wid = threadIdx.x >> 5, lane = threadIdx.x & 31;
    if (lane == 0) { shs[wid] = s; shs2[wid] = s2; }
    __syncthreads();
    if (threadIdx.x == 0) {
        float a = 0.f, c = 0.f;
        for (int i = 0; i < (int)(blockDim.x >> 5); i++) { a += shs[i]; c += shs2[i]; }
        g_part[bg][sl][0] = a;
        g_part[bg][sl][1] = c;
    }
}

// ---------------- 1b) GroupNorm apply (per batch) ----------------
__global__ __launch_bounds__(256) void gn_apply(const float* __restrict__ x,
                                                const float* __restrict__ w,
                                                const float* __restrict__ b,
                                                int bb) {
    __shared__ float tile[64][68];
    int g  = blockIdx.y;
    int bg = bb*NG + g;
    float s = 0.f, s2 = 0.f;
    #pragma unroll
    for (int i = 0; i < 8; i++) { s += g_part[bg][i][0]; s2 += g_part[bg][i][1]; }
    const float invN = 1.f / (float)(CPG*HW);
    float mean = s * invN;
    float var  = s2 * invN - mean*mean;
    float rstd = rsqrtf(var + EPS);

    int n0 = blockIdx.x * 64;
    int tid = threadIdx.x;
    size_t base = (size_t)bg * CPG * HW;
    #pragma unroll
    for (int it = 0; it < 4; ++it) {
        int idx = tid + it*256;
        int r = idx >> 4, c = idx & 15;
        float4 v = *(const float4*)(x + base + (size_t)r*HW + n0 + c*4);
        int ch = g*CPG + r;
        float sc = w[ch] * rstd;
        float bo = b[ch] - mean * sc;
        float4 o;
        o.x = v.x*sc + bo; o.y = v.y*sc + bo;
        o.z = v.z*sc + bo; o.w = v.w*sc + bo;
        *(float4*)&tile[r][c*4] = o;
    }
    __syncthreads();
    int warp = tid >> 5, lane = tid & 31;
    __nv_bfloat16* outp = g_xn + (size_t)bb*HW*CH;
    #pragma unroll
    for (int rr = 0; rr < 8; ++rr) {
        int n = warp*8 + rr;
        float a0 = tile[lane*2][n], a1 = tile[lane*2+1][n];
        *(uint32_t*)(outp + (size_t)(n0+n)*CH + g*CPG + lane*2) = packbf(a0, a1);
    }
}

// ---------------- GEMM core: 3-stage cp.async ring (R11 exact) ------------
#define GPAD 40
#define GSTG (128*GPAD*2)
__device__ __forceinline__ void gcp_tile(uint32_t dst, const __nv_bfloat16* src, int k0) {
    int tid = threadIdx.x;
    int r = tid >> 1, hb = (tid & 1) * 32;
    const char* sp = (const char*)(src + (size_t)r*512 + k0);
    cpasync16(dst + r*80 + hb,      sp + hb);
    cpasync16(dst + r*80 + hb + 16, sp + hb + 16);
}

__device__ __forceinline__ void gemm_core(const __nv_bfloat16* __restrict__ Ag,
                                          const __nv_bfloat16* __restrict__ Bg,
                                          char* As, char* Bs,
                                          float acc[4][4][4]) {
    int tid = threadIdx.x;
    int warp = tid >> 5, lane = tid & 31;
    int wm = (warp >> 2) * 64, wn = (warp & 3) * 32;
    uint32_t as_b = (uint32_t)__cvta_generic_to_shared(As);
    uint32_t bs_b = (uint32_t)__cvta_generic_to_shared(Bs);
    int a_row = ((lane>>3)&1)*8 + (lane&7);
    int a_col = (lane>>4)*8;
    int b_row = ((lane>>4)&1)*8 + (lane&7);
    int b_col = ((lane>>3)&1)*8;

    gcp_tile(as_b,        Ag, 0);  gcp_tile(bs_b,        Bg, 0);  CP_COMMIT();
    gcp_tile(as_b + GSTG, Ag, 32); gcp_tile(bs_b + GSTG, Bg, 32); CP_COMMIT();

    int st = 0;
    for (int k0 = 0; k0 < 512; k0 += 32) {
        if (k0 == 480) { CP_WAIT0(); } else { CP_WAIT1(); }
        __syncthreads();
        if (k0 + 64 < 512) {
            int s2 = st + 2; if (s2 >= 3) s2 -= 3;
            gcp_tile(as_b + s2*GSTG, Ag, k0 + 64);
            gcp_tile(bs_b + s2*GSTG, Bg, k0 + 64);
            CP_COMMIT();
        }
        uint32_t ab = as_b + st*GSTG, bb = bs_b + st*GSTG;
        #pragma unroll
        for (int ks = 0; ks < 32; ks += 16) {
            uint32_t af[4][4];
            #pragma unroll
            for (int mi = 0; mi < 4; ++mi)
                ldsm_x4(af[mi][0], af[mi][1], af[mi][2], af[mi][3],
                        ab + ((wm + 16*mi + a_row)*GPAD + ks + a_col)*2);
            #pragma unroll
            for (int np = 0; np < 2; ++np) {
                uint32_t b00, b01, b10, b11;
                ldsm_x4(b00, b01, b10, b11,
                        bb + ((wn + 16*np + b_row)*GPAD + ks + b_col)*2);
                #pragma unroll
                for (int mi = 0; mi < 4; ++mi) {
                    mma16816(acc[mi][2*np],   af[mi], b00, b01);
                    mma16816(acc[mi][2*np+1], af[mi], b10, b11);
                }
            }
        }
        st = st + 1; if (st >= 3) st = 0;
    }
}

// ---------------- 2) QKV GEMM (per batch) ----------------
__global__ __launch_bounds__(256) void gemm_qkv(const float* __restrict__ bias, int z) {
    extern __shared__ char gsm[];
    char* As = gsm;
    char* Bs = gsm + 3*GSTG;
    int m0 = blockIdx.y * 128, n0 = blockIdx.x * 128;
    float acc[4][4][4] = {};
    gemm_core(g_wq + (size_t)m0*512, g_xn + (size_t)z*HW*CH + (size_t)n0*512,
              As, Bs, acc);

    int warp = threadIdx.x >> 5, lane = threadIdx.x & 31;
    int g = lane >> 2, t = lane & 3;
    int wm = (warp >> 2) * 64, wn = (warp & 3) * 32;

    #pragma unroll
    for (int mi = 0; mi < 4; ++mi) {
        #pragma unroll
        for (int rr = 0; rr < 2; ++rr) {
            int o = m0 + wm + 16*mi + g + rr*8;
            float bi = bias[o];
            int h = (o >> 6) & 7, d = o & 63;
            size_t base = ((size_t)(z*NH + h)*HD + d)*HW;
            #pragma unroll
            for (int nj = 0; nj < 4; ++nj) {
                int n = n0 + wn + 8*nj + 2*t;
                float v0 = acc[mi][nj][rr*2 + 0] + bi;
                float v1 = acc[mi][nj][rr*2 + 1] + bi;
                if (o < 512) {
                    *(uint32_t*)&g_q[base + n] = packbf(v0*QSCALE, v1*QSCALE);
                } else if (o < 1024) {
                    *(uint32_t*)&g_k[base + n] = packbf(v0, v1);
                } else {
                    __half2 p = __floats2half2_rn(v0, v1);
                    *(uint32_t*)&g_v[base + n] = *(uint32_t*)&p;
                }
            }
        }
    }
}

// ---------------- 3) flash attention (per batch, R11 exact) --------------
#define QPITCH 264
#define KVP    72
#define ASTG   (64*KVP*2)
__device__ __forceinline__ void kv_cp(uint32_t kd, uint32_t vd,
                                      const __nv_bfloat16* Kg, const __half* Vg,
                                      int m0k) {
    int t = threadIdx.x; int r = t >> 2, cb = (t & 3) * 32;
    const char* ks = (const char*)Kg + ((size_t)r*HW + m0k)*2;
    uint32_t kdst = kd + r*(KVP*2) + cb;
    cpasync16(kdst,      ks + cb);
    cpasync16(kdst + 16, ks + cb + 16);
    const char* vs = (const char*)Vg + ((size_t)r*HW + m0k)*2;
    uint32_t vdst = vd + r*(KVP*2) + cb;
    cpasync16(vdst,      vs + cb);
    cpasync16(vdst + 16, vs + cb + 16);
}

__global__ __launch_bounds__(256) void attn_kernel(int zb) {
    extern __shared__ char sm[];
    char* Qsm = sm;                               // [64 d][QPITCH n] bf16
    char* Ksm = sm + 64*QPITCH*2;                 // 2 stages
    char* Vsm = Ksm + 2*ASTG;                     // 2 stages
    uint32_t qs_b = (uint32_t)__cvta_generic_to_shared(Qsm);
    uint32_t ks_b = (uint32_t)__cvta_generic_to_shared(Ksm);
    uint32_t vs_b = (uint32_t)__cvta_generic_to_shared(Vsm);

    int bh = zb*NH + blockIdx.y, n0 = blockIdx.x * 256;
    const __nv_bfloat16* Qg = g_q + (size_t)bh*HD*HW;
    const __nv_bfloat16* Kg = g_k + (size_t)bh*HD*HW;
    const __half*        Vg = g_v + (size_t)bh*HD*HW;

    int tid = threadIdx.x, warp = tid >> 5, lane = tid & 31;
    int g = lane >> 2, t = lane & 3;
    int qrow = warp * 32;
    int aq_row = ((lane>>4)&1)*8 + (lane&7);
    int aq_col = ((lane>>3)&1)*8;
    int bk_row = ((lane>>3)&1)*8 + (lane&7);
    int bk_col = ((lane>>4)&1)*8;
    int bv_row = ((lane>>4)&1)*8 + (lane&7);
    int bv_col = ((lane>>3)&1)*8;

    kv_cp(ks_b, vs_b, Kg, Vg, 0);
    CP_COMMIT();

    {   // Q tile: 64 rows x 256 cols bf16
        int r = tid >> 2, c = (tid & 3) * 64;
        #pragma unroll
        for (int i = 0; i < 8; ++i)
            *(uint4*)(Qsm + ((size_t)r*QPITCH + c + i*8)*2) =
                *(const uint4*)(Qg + (size_t)r*HW + n0 + c + i*8);
    }
    __syncthreads();

    uint32_t qf[2][4][4];
    #pragma unroll
    for (int mi = 0; mi < 2; ++mi)
        #pragma unroll
        for (int ks = 0; ks < 4; ++ks)
            ldsm_x4_t(qf[mi][ks][0], qf[mi][ks][1], qf[mi][ks][2], qf[mi][ks][3],
                      qs_b + ((ks*16 + aq_row)*QPITCH + qrow + 16*mi + aq_col)*2);

    float o_acc[2][8][4] = {};
    float l_lo[2] = {0.f, 0.f}, l_hi[2] = {0.f, 0.f};

    for (int kb = 0; kb < 64; ++kb) {
        CP_WAIT0();
        __syncthreads();
        if (kb < 63) {
            int s2 = (kb + 1) & 1;
            kv_cp(ks_b + s2*ASTG, vs_b + s2*ASTG, Kg, Vg, (kb+1)*64);
            CP_COMMIT();
        }
        uint32_t kbb = ks_b + (kb & 1)*ASTG;
        uint32_t vbb = vs_b + (kb & 1)*ASTG;

        #pragma unroll
        for (int jp = 0; jp < 4; ++jp) {
            float s[2][2][4];
            #pragma unroll
            for (int mi = 0; mi < 2; ++mi)
                #pragma unroll
                for (int hh = 0; hh < 2; ++hh)
                    #pragma unroll
                    for (int i = 0; i < 4; ++i) s[mi][hh][i] = -MFIX;
            #pragma unroll
            for (int ks = 0; ks < 4; ++ks) {
                uint32_t b00, b01, b10, b11;
                ldsm_x4_t(b00, b01, b10, b11,
                          kbb + ((ks*16 + bk_row)*KVP + jp*16 + bk_col)*2);
                #pragma unroll
                for (int mi = 0; mi < 2; ++mi) {
                    mma16816(s[mi][0], qf[mi][ks], b00, b01);
                    mma16816(s[mi][1], qf[mi][ks], b10, b11);
                }
            }
            uint32_t pa[2][4];
            #pragma unroll
            for (int mi = 0; mi < 2; ++mi) {
                pa[mi][0] = ex2h2(s[mi][0][0], s[mi][0][1]);
                pa[mi][1] = ex2h2(s[mi][0][2], s[mi][0][3]);
                pa[mi][2] = ex2h2(s[mi][1][0], s[mi][1][1]);
                pa[mi][3] = ex2h2(s[mi][1][2], s[mi][1][3]);
                uint32_t rl = hadd2u(pa[mi][0], pa[mi][2]);
                uint32_t rh = hadd2u(pa[mi][1], pa[mi][3]);
                float2 fl = h22f2(rl), fh = h22f2(rh);
                l_lo[mi] += fl.x + fl.y;
                l_hi[mi] += fh.x + fh.y;
            }
            #pragma unroll
            for (int cp = 0; cp < 4; ++cp) {
                uint32_t v00, v01, v10, v11;
                ldsm_x4(v00, v01, v10, v11,
                        vbb + ((16*cp + bv_row)*KVP + jp*16 + bv_col)*2);
                #pragma unroll
                for (int mi = 0; mi < 2; ++mi) {
                    mma16816h(o_acc[mi][2*cp],   pa[mi], v00, v01);
                    mma16816h(o_acc[mi][2*cp+1], pa[mi], v10, v11);
                }
            }
        }
    }

    int h = bh & 7;
    __nv_bfloat16* Og = g_o + (size_t)zb*HW*CH;
    #pragma unroll
    for (int mi = 0; mi < 2; ++mi) {
        float ll = l_lo[mi], lh = l_hi[mi];
        ll += __shfl_xor_sync(0xffffffffu, ll, 1);
        ll += __shfl_xor_sync(0xffffffffu, ll, 2);
        lh += __shfl_xor_sync(0xffffffffu, lh, 1);
        lh += __shfl_xor_sync(0xffffffffu, lh, 2);
        float inv_lo = 1.f / ll, inv_hi = 1.f / lh;
        int r_lo = n0 + qrow + 16*mi + g, r_hi = r_lo + 8;
        #pragma unroll
        for (int c = 0; c < 8; ++c) {
            int col = h*64 + 8*c + 2*t;
            *(uint32_t*)(Og + (size_t)r_lo*CH + col) =
                packbf(o_acc[mi][c][0]*inv_lo, o_acc[mi][c][1]*inv_lo);
            *(uint32_t*)(Og + (size_t)r_hi*CH + col) =
                packbf(o_acc[mi][c][2]*inv_hi, o_acc[mi][c][3]*inv_hi);
        }
    }
}

// ---------------- 4) proj GEMM + bias + residual (per batch) -------------
__global__ __launch_bounds__(256) void gemm_proj(const float* __restrict__ bias,
                                                 const float* __restrict__ x,
                                                 float* __restrict__ out, int z) {
    extern __shared__ char gsm[];
    char* As = gsm;
    char* Bs = gsm + 3*GSTG;
    int m0 = blockIdx.y * 128, n0 = blockIdx.x * 128;
    float acc[4][4][4] = {};
    gemm_core(g_wp + (size_t)m0*512, g_o + (size_t)z*HW*CH + (size_t)n0*512,
              As, Bs, acc);

    int warp = threadIdx.x >> 5, lane = threadIdx.x & 31;
    int g = lane >> 2, t = lane & 3;
    int wm = (warp >> 2) * 64, wn = (warp & 3) * 32;

    #pragma unroll
    for (int mi = 0; mi < 4; ++mi) {
        #pragma unroll
        for (int rr = 0; rr < 2; ++rr) {
            int c = m0 + wm + 16*mi + g + rr*8;
            float bi = bias[c];
            size_t rowb = ((size_t)z*CH + c)*HW;
            #pragma unroll
            for (int nj = 0; nj < 4; ++nj) {
                int n = n0 + wn + 8*nj + 2*t;
                float2 xr = *(const float2*)(x + rowb + n);
                float2 o;
                o.x = acc[mi][nj][rr*2 + 0] + bi + xr.x;
                o.y = acc[mi][nj][rr*2 + 1] + bi + xr.y;
                *(float2*)(out + rowb + n) = o;
            }
        }
    }
}

// ---------------- launch: two-stream batch pipeline ----------------
extern "C" void kernel_launch(void* const* d_in, const int* in_sizes, int n_in,
                              void* d_out, int out_size) {
    const float* x      = (const float*)d_in[0];
    const float* norm_w = (const float*)d_in[1];
    const float* norm_b = (const float*)d_in[2];
    const float* qkv_w  = (const float*)d_in[3];
    const float* qkv_b  = (const float*)d_in[4];
    const float* proj_w = (const float*)d_in[5];
    const float* proj_b = (const float*)d_in[6];
    float* out = (float*)d_out;

    const int ASMEM = 64*QPITCH*2 + 4*ASTG;   // 70656
    const int GSMEM = 6*GSTG;                  // 61440
    cudaFuncSetAttribute(attn_kernel,
                         cudaFuncAttributeMaxDynamicSharedMemorySize, ASMEM);
    cudaFuncSetAttribute(gemm_qkv,
                         cudaFuncAttributeMaxDynamicSharedMemorySize, GSMEM);
    cudaFuncSetAttribute(gemm_proj,
                         cudaFuncAttributeMaxDynamicSharedMemorySize, GSMEM);

    static cudaStream_t s1 = nullptr;
    static cudaEvent_t evFork = nullptr, evJoin = nullptr;
    if (s1 == nullptr) {
        cudaStreamCreateWithFlags(&s1, cudaStreamNonBlocking);
        cudaEventCreateWithFlags(&evFork, cudaEventDisableTiming);
        cudaEventCreateWithFlags(&evJoin, cudaEventDisableTiming);
    }

    // shared prologue on the main (capture) stream
    gn_reduce<<<128 + 1024, 256>>>(x, qkv_w, proj_w);

    // fork: stream s1 handles batch 1
    cudaEventRecord(evFork, 0);
    cudaStreamWaitEvent(s1, evFork, 0);

    // batch 0 chain on main stream
    gn_apply<<<dim3(HW/64, NG), 256>>>(x, norm_w, norm_b, 0);
    gemm_qkv<<<dim3(HW/128, 12), 256, GSMEM>>>(qkv_b, 0);
    attn_kernel<<<dim3(HW/256, NH), 256, ASMEM>>>(0);
    gemm_proj<<<dim3(HW/128, 4), 256, GSMEM>>>(proj_b, x, out, 0);

    // batch 1 chain on s1
    gn_apply<<<dim3(HW/64, NG), 256, 0, s1>>>(x, norm_w, norm_b, 1);
    gemm_qkv<<<dim3(HW/128, 12), 256, GSMEM, s1>>>(qkv_b, 1);
    attn_kernel<<<dim3(HW/256, NH), 256, ASMEM, s1>>>(1);
    gemm_proj<<<dim3(HW/128, 4), 256, GSMEM, s1>>>(proj_b, x, out, 1);

    // join
    cudaEventRecord(evJoin, s1);
    cudaStreamWaitEvent(0, evJoin, 0);
}

// round 17
// speedup vs baseline: 1.1301x; 1.0088x over previous
#include <cuda_runtime.h>
#include <cuda_bf16.h>
#include <cuda_fp16.h>
#include <math.h>
#include <stdint.h>

#define BATCH 2
#define CH    512
#define NH    8
#define HD    64
#define HW    4096
#define NG    8
#define CPG   64
#define EPS   1e-5f
#define LOG2E 1.4426950408889634f
#define QSCALE (0.125f * LOG2E)
#define MFIX  8.0f

// ---------------- scratch ----------------
__device__ __align__(128) __nv_bfloat16 g_xn[(size_t)BATCH*HW*CH];   // [b][n][c]
__device__ __align__(128) __nv_bfloat16 g_q[(size_t)BATCH*NH*HD*HW]; // [bh][d][n] scaled
__device__ __align__(128) __nv_bfloat16 g_k[(size_t)BATCH*NH*HD*HW]; // [bh][d][n]
__device__ __align__(128) __half        g_v[(size_t)BATCH*NH*HD*HW]; // [bh][d][n] fp16
__device__ __align__(128) __nv_bfloat16 g_o[(size_t)BATCH*HW*CH];    // [b][n][c]
__device__ __align__(128) __nv_bfloat16 g_wq[3*CH*CH];
__device__ __align__(128) __nv_bfloat16 g_wp[CH*CH];
__device__ float g_part[BATCH*NG][8][2];

// ---------------- helpers ----------------
__device__ __forceinline__ float warpSum(float v) {
    #pragma unroll
    for (int o = 16; o > 0; o >>= 1) v += __shfl_xor_sync(0xffffffffu, v, o);
    return v;
}
__device__ __forceinline__ uint32_t packbf(float a, float b) {
    __nv_bfloat162 h = __floats2bfloat162_rn(a, b);
    return *(uint32_t*)&h;
}
__device__ __forceinline__ uint32_t ex2h2(float lo, float hi) {
    uint32_t h;
    asm("cvt.rn.f16x2.f32 %0, %1, %2;" : "=r"(h) : "f"(hi), "f"(lo));
    asm("ex2.approx.f16x2 %0, %0;" : "+r"(h));
    return h;
}
__device__ __forceinline__ uint32_t hadd2u(uint32_t x, uint32_t y) {
    uint32_t d; asm("add.rn.f16x2 %0, %1, %2;" : "=r"(d) : "r"(x), "r"(y));
    return d;
}
__device__ __forceinline__ float2 h22f2(uint32_t h) {
    __half2 v = *(__half2*)&h;
    return __half22float2(v);
}
__device__ __forceinline__ void ldsm_x4(uint32_t& r0, uint32_t& r1,
                                        uint32_t& r2, uint32_t& r3, uint32_t addr) {
    asm volatile("ldmatrix.sync.aligned.m8n8.x4.shared.b16 {%0,%1,%2,%3}, [%4];"
                 : "=r"(r0), "=r"(r1), "=r"(r2), "=r"(r3) : "r"(addr));
}
__device__ __forceinline__ void ldsm_x4_t(uint32_t& r0, uint32_t& r1,
                                          uint32_t& r2, uint32_t& r3, uint32_t addr) {
    asm volatile("ldmatrix.sync.aligned.m8n8.x4.trans.shared.b16 {%0,%1,%2,%3}, [%4];"
                 : "=r"(r0), "=r"(r1), "=r"(r2), "=r"(r3) : "r"(addr));
}
__device__ __forceinline__ void cpasync16(uint32_t dst, const void* src) {
    asm volatile("cp.async.ca.shared.global [%0], [%1], 16;" :: "r"(dst), "l"(src) : "memory");
}
#define CP_COMMIT() asm volatile("cp.async.commit_group;" ::: "memory")
#define CP_WAIT0()  asm volatile("cp.async.wait_group 0;" ::: "memory")
#define CP_WAIT1()  asm volatile("cp.async.wait_group 1;" ::: "memory")
__device__ __forceinline__ void mma16816(float c[4], const uint32_t a[4],
                                         uint32_t b0, uint32_t b1) {
    asm volatile(
        "mma.sync.aligned.m16n8k16.row.col.f32.bf16.bf16.f32 "
        "{%0,%1,%2,%3}, {%4,%5,%6,%7}, {%8,%9}, {%0,%1,%2,%3};"
        : "+f"(c[0]), "+f"(c[1]), "+f"(c[2]), "+f"(c[3])
        : "r"(a[0]), "r"(a[1]), "r"(a[2]), "r"(a[3]), "r"(b0), "r"(b1));
}
__device__ __forceinline__ void mma16816h(float c[4], const uint32_t a[4],
                                          uint32_t b0, uint32_t b1) {
    asm volatile(
        "mma.sync.aligned.m16n8k16.row.col.f32.f16.f16.f32 "
        "{%0,%1,%2,%3}, {%4,%5,%6,%7}, {%8,%9}, {%0,%1,%2,%3};"
        : "+f"(c[0]), "+f"(c[1]), "+f"(c[2]), "+f"(c[3])
        : "r"(a[0]), "r"(a[1]), "r"(a[2]), "r"(a[3]), "r"(b0), "r"(b1));
}

// ---------------- 1a) GroupNorm partial reduce + weight convert (both b) --
__global__ void gn_reduce(const float* __restrict__ x,
                          const float* __restrict__ qw,
                          const float* __restrict__ pw) {
    if (blockIdx.x >= 128) {
        int i = (blockIdx.x - 128) * 256 + threadIdx.x;
        if (i < 196608) {
            float4 v = ((const float4*)qw)[i];
            uint2 p; p.x = packbf(v.x, v.y); p.y = packbf(v.z, v.w);
            *(uint2*)(g_wq + (size_t)i*4) = p;
        } else {
            int j = i - 196608;
            float4 v = ((const float4*)pw)[j];
            uint2 p; p.x = packbf(v.x, v.y); p.y = packbf(v.z, v.w);
            *(uint2*)(g_wp + (size_t)j*4) = p;
        }
        return;
    }
    int bg = blockIdx.x >> 3;
    int sl = blockIdx.x & 7;
    size_t base = (size_t)bg * CPG * HW + (size_t)sl * (CPG*HW/8);
    const float4* x4 = (const float4*)(x + base);
    const int NV = CPG*HW/8/4;

    float s = 0.f, s2 = 0.f;
    for (int i = threadIdx.x; i < NV; i += blockDim.x) {
        float4 t = x4[i];
        s  += t.x + t.y + t.z + t.w;
        s2 += t.x*t.x + t.y*t.y + t.z*t.z + t.w*t.w;
    }
    __shared__ float shs[8], shs2[8];
    s = warpSum(s); s2 = warpSum(s2);
    int wid = threadIdx.x >> 5, lane = threadIdx.x & 31;
    if (lane == 0) { shs[wid] = s; shs2[wid] = s2; }
    __syncthreads();
    if (threadIdx.x == 0) {
        float a = 0.f, c = 0.f;
        for (int i = 0; i < (int)(blockDim.x >> 5); i++) { a += shs[i]; c += shs2[i]; }
        g_part[bg][sl][0] = a;
        g_part[bg][sl][1] = c;
    }
}

// ---------------- 1b) GroupNorm apply (per batch) ----------------
__global__ __launch_bounds__(256) void gn_apply(const float* __restrict__ x,
                                                const float* __restrict__ w,
                                                const float* __restrict__ b,
                                                int bb) {
    __shared__ float tile[64][68];
    int g  = blockIdx.y;
    int bg = bb*NG + g;
    float s = 0.f, s2 = 0.f;
    #pragma unroll
    for (int i = 0; i < 8; i++) { s += g_part[bg][i][0]; s2 += g_part[bg][i][1]; }
    const float invN = 1.f / (float)(CPG*HW);
    float mean = s * invN;
    float var  = s2 * invN - mean*mean;
    float rstd = rsqrtf(var + EPS);

    int n0 = blockIdx.x * 64;
    int tid = threadIdx.x;
    size_t base = (size_t)bg * CPG * HW;
    #pragma unroll
    for (int it = 0; it < 4; ++it) {
        int idx = tid + it*256;
        int r = idx >> 4, c = idx & 15;
        float4 v = *(const float4*)(x + base + (size_t)r*HW + n0 + c*4);
        int ch = g*CPG + r;
        float sc = w[ch] * rstd;
        float bo = b[ch] - mean * sc;
        float4 o;
        o.x = v.x*sc + bo; o.y = v.y*sc + bo;
        o.z = v.z*sc + bo; o.w = v.w*sc + bo;
        *(float4*)&tile[r][c*4] = o;
    }
    __syncthreads();
    int warp = tid >> 5, lane = tid & 31;
    __nv_bfloat16* outp = g_xn + (size_t)bb*HW*CH;
    #pragma unroll
    for (int rr = 0; rr < 8; ++rr) {
        int n = warp*8 + rr;
        float a0 = tile[lane*2][n], a1 = tile[lane*2+1][n];
        *(uint32_t*)(outp + (size_t)(n0+n)*CH + g*CPG + lane*2) = packbf(a0, a1);
    }
}

// ---------------- GEMM core: 3-stage cp.async ring (R11 exact) ------------
#define GPAD 40
#define GSTG (128*GPAD*2)
__device__ __forceinline__ void gcp_tile(uint32_t dst, const __nv_bfloat16* src, int k0) {
    int tid = threadIdx.x;
    int r = tid >> 1, hb = (tid & 1) * 32;
    const char* sp = (const char*)(src + (size_t)r*512 + k0);
    cpasync16(dst + r*80 + hb,      sp + hb);
    cpasync16(dst + r*80 + hb + 16, sp + hb + 16);
}

__device__ __forceinline__ void gemm_core(const __nv_bfloat16* __restrict__ Ag,
                                          const __nv_bfloat16* __restrict__ Bg,
                                          char* As, char* Bs,
                                          float acc[4][4][4]) {
    int tid = threadIdx.x;
    int warp = tid >> 5, lane = tid & 31;
    int wm = (warp >> 2) * 64, wn = (warp & 3) * 32;
    uint32_t as_b = (uint32_t)__cvta_generic_to_shared(As);
    uint32_t bs_b = (uint32_t)__cvta_generic_to_shared(Bs);
    int a_row = ((lane>>3)&1)*8 + (lane&7);
    int a_col = (lane>>4)*8;
    int b_row = ((lane>>4)&1)*8 + (lane&7);
    int b_col = ((lane>>3)&1)*8;

    gcp_tile(as_b,        Ag, 0);  gcp_tile(bs_b,        Bg, 0);  CP_COMMIT();
    gcp_tile(as_b + GSTG, Ag, 32); gcp_tile(bs_b + GSTG, Bg, 32); CP_COMMIT();

    int st = 0;
    for (int k0 = 0; k0 < 512; k0 += 32) {
        if (k0 == 480) { CP_WAIT0(); } else { CP_WAIT1(); }
        __syncthreads();
        if (k0 + 64 < 512) {
            int s2 = st + 2; if (s2 >= 3) s2 -= 3;
            gcp_tile(as_b + s2*GSTG, Ag, k0 + 64);
            gcp_tile(bs_b + s2*GSTG, Bg, k0 + 64);
            CP_COMMIT();
        }
        uint32_t ab = as_b + st*GSTG, bb = bs_b + st*GSTG;
        #pragma unroll
        for (int ks = 0; ks < 32; ks += 16) {
            uint32_t af[4][4];
            #pragma unroll
            for (int mi = 0; mi < 4; ++mi)
                ldsm_x4(af[mi][0], af[mi][1], af[mi][2], af[mi][3],
                        ab + ((wm + 16*mi + a_row)*GPAD + ks + a_col)*2);
            #pragma unroll
            for (int np = 0; np < 2; ++np) {
                uint32_t b00, b01, b10, b11;
                ldsm_x4(b00, b01, b10, b11,
                        bb + ((wn + 16*np + b_row)*GPAD + ks + b_col)*2);
                #pragma unroll
                for (int mi = 0; mi < 4; ++mi) {
                    mma16816(acc[mi][2*np],   af[mi], b00, b01);
                    mma16816(acc[mi][2*np+1], af[mi], b10, b11);
                }
            }
        }
        st = st + 1; if (st >= 3) st = 0;
    }
}

// ---------------- 2) QKV GEMM (per batch) ----------------
__global__ __launch_bounds__(256) void gemm_qkv(const float* __restrict__ bias, int z) {
    extern __shared__ char gsm[];
    char* As = gsm;
    char* Bs = gsm + 3*GSTG;
    int m0 = blockIdx.y * 128, n0 = blockIdx.x * 128;
    float acc[4][4][4] = {};
    gemm_core(g_wq + (size_t)m0*512, g_xn + (size_t)z*HW*CH + (size_t)n0*512,
              As, Bs, acc);

    int warp = threadIdx.x >> 5, lane = threadIdx.x & 31;
    int g = lane >> 2, t = lane & 3;
    int wm = (warp >> 2) * 64, wn = (warp & 3) * 32;

    #pragma unroll
    for (int mi = 0; mi < 4; ++mi) {
        #pragma unroll
        for (int rr = 0; rr < 2; ++rr) {
            int o = m0 + wm + 16*mi + g + rr*8;
            float bi = bias[o];
            int h = (o >> 6) & 7, d = o & 63;
            size_t base = ((size_t)(z*NH + h)*HD + d)*HW;
            #pragma unroll
            for (int nj = 0; nj < 4; ++nj) {
                int n = n0 + wn + 8*nj + 2*t;
                float v0 = acc[mi][nj][rr*2 + 0] + bi;
                float v1 = acc[mi][nj][rr*2 + 1] + bi;
                if (o < 512) {
                    *(uint32_t*)&g_q[base + n] = packbf(v0*QSCALE, v1*QSCALE);
                } else if (o < 1024) {
                    *(uint32_t*)&g_k[base + n] = packbf(v0, v1);
                } else {
                    __half2 p = __floats2half2_rn(v0, v1);
                    *(uint32_t*)&g_v[base + n] = *(uint32_t*)&p;
                }
            }
        }
    }
}

// ---------------- 3) flash attention (per batch, warp-phase staggered) ----
#define QPITCH 264
#define KVP    72
#define ASTG   (64*KVP*2)
__device__ __forceinline__ void kv_cp(uint32_t kd, uint32_t vd,
                                      const __nv_bfloat16* Kg, const __half* Vg,
                                      int m0k) {
    int t = threadIdx.x; int r = t >> 2, cb = (t & 3) * 32;
    const char* ks = (const char*)Kg + ((size_t)r*HW + m0k)*2;
    uint32_t kdst = kd + r*(KVP*2) + cb;
    cpasync16(kdst,      ks + cb);
    cpasync16(kdst + 16, ks + cb + 16);
    const char* vs = (const char*)Vg + ((size_t)r*HW + m0k)*2;
    uint32_t vdst = vd + r*(KVP*2) + cb;
    cpasync16(vdst,      vs + cb);
    cpasync16(vdst + 16, vs + cb + 16);
}

__global__ __launch_bounds__(256) void attn_kernel(int zb) {
    extern __shared__ char sm[];
    char* Qsm = sm;                               // [64 d][QPITCH n] bf16
    char* Ksm = sm + 64*QPITCH*2;                 // 2 stages
    char* Vsm = Ksm + 2*ASTG;                     // 2 stages
    uint32_t qs_b = (uint32_t)__cvta_generic_to_shared(Qsm);
    uint32_t ks_b = (uint32_t)__cvta_generic_to_shared(Ksm);
    uint32_t vs_b = (uint32_t)__cvta_generic_to_shared(Vsm);

    int bh = zb*NH + blockIdx.y, n0 = blockIdx.x * 256;
    const __nv_bfloat16* Qg = g_q + (size_t)bh*HD*HW;
    const __nv_bfloat16* Kg = g_k + (size_t)bh*HD*HW;
    const __half*        Vg = g_v + (size_t)bh*HD*HW;

    int tid = threadIdx.x, warp = tid >> 5, lane = tid & 31;
    int g = lane >> 2, t = lane & 3;
    int qrow = warp * 32;
    int jpofs = (warp >> 2) * 2;                  // co-SMSP warps (w, w+4) offset 0 vs 2
    int aq_row = ((lane>>4)&1)*8 + (lane&7);
    int aq_col = ((lane>>3)&1)*8;
    int bk_row = ((lane>>3)&1)*8 + (lane&7);
    int bk_col = ((lane>>4)&1)*8;
    int bv_row = ((lane>>4)&1)*8 + (lane&7);
    int bv_col = ((lane>>3)&1)*8;

    kv_cp(ks_b, vs_b, Kg, Vg, 0);
    CP_COMMIT();

    {   // Q tile: 64 rows x 256 cols bf16
        int r = tid >> 2, c = (tid & 3) * 64;
        #pragma unroll
        for (int i = 0; i < 8; ++i)
            *(uint4*)(Qsm + ((size_t)r*QPITCH + c + i*8)*2) =
                *(const uint4*)(Qg + (size_t)r*HW + n0 + c + i*8);
    }
    __syncthreads();

    uint32_t qf[2][4][4];
    #pragma unroll
    for (int mi = 0; mi < 2; ++mi)
        #pragma unroll
        for (int ks = 0; ks < 4; ++ks)
            ldsm_x4_t(qf[mi][ks][0], qf[mi][ks][1], qf[mi][ks][2], qf[mi][ks][3],
                      qs_b + ((ks*16 + aq_row)*QPITCH + qrow + 16*mi + aq_col)*2);

    float o_acc[2][8][4] = {};
    float l_lo[2] = {0.f, 0.f}, l_hi[2] = {0.f, 0.f};

    for (int kb = 0; kb < 64; ++kb) {
        CP_WAIT0();
        __syncthreads();
        if (kb < 63) {
            int s2 = (kb + 1) & 1;
            kv_cp(ks_b + s2*ASTG, vs_b + s2*ASTG, Kg, Vg, (kb+1)*64);
            CP_COMMIT();
        }
        uint32_t kbb = ks_b + (kb & 1)*ASTG;
        uint32_t vbb = vs_b + (kb & 1)*ASTG;

        #pragma unroll
        for (int j = 0; j < 4; ++j) {
            int jp = (j + jpofs) & 3;     // phase-staggered chunk order per SMSP pair
            float s[2][2][4];
            #pragma unroll
            for (int mi = 0; mi < 2; ++mi)
                #pragma unroll
                for (int hh = 0; hh < 2; ++hh)
                    #pragma unroll
                    for (int i = 0; i < 4; ++i) s[mi][hh][i] = -MFIX;
            #pragma unroll
            for (int ks = 0; ks < 4; ++ks) {
                uint32_t b00, b01, b10, b11;
                ldsm_x4_t(b00, b01, b10, b11,
                          kbb + ((ks*16 + bk_row)*KVP + jp*16 + bk_col)*2);
                #pragma unroll
                for (int mi = 0; mi < 2; ++mi) {
                    mma16816(s[mi][0], qf[mi][ks], b00, b01);
                    mma16816(s[mi][1], qf[mi][ks], b10, b11);
                }
            }
            uint32_t pa[2][4];
            #pragma unroll
            for (int mi = 0; mi < 2; ++mi) {
                pa[mi][0] = ex2h2(s[mi][0][0], s[mi][0][1]);
                pa[mi][1] = ex2h2(s[mi][0][2], s[mi][0][3]);
                pa[mi][2] = ex2h2(s[mi][1][0], s[mi][1][1]);
                pa[mi][3] = ex2h2(s[mi][1][2], s[mi][1][3]);
                uint32_t rl = hadd2u(pa[mi][0], pa[mi][2]);
                uint32_t rh = hadd2u(pa[mi][1], pa[mi][3]);
                float2 fl = h22f2(rl), fh = h22f2(rh);
                l_lo[mi] += fl.x + fl.y;
                l_hi[mi] += fh.x + fh.y;
            }
            #pragma unroll
            for (int cp = 0; cp < 4; ++cp) {
                uint32_t v00, v01, v10, v11;
                ldsm_x4(v00, v01, v10, v11,
                        vbb + ((16*cp + bv_row)*KVP + jp*16 + bv_col)*2);
                #pragma unroll
                for (int mi = 0; mi < 2; ++mi) {
                    mma16816h(o_acc[mi][2*cp],   pa[mi], v00, v01);
                    mma16816h(o_acc[mi][2*cp+1], pa[mi], v10, v11);
                }
            }
        }
    }

    int h = bh & 7;
    __nv_bfloat16* Og = g_o + (size_t)zb*HW*CH;
    #pragma unroll
    for (int mi = 0; mi < 2; ++mi) {
        float ll = l_lo[mi], lh = l_hi[mi];
        ll += __shfl_xor_sync(0xffffffffu, ll, 1);
        ll += __shfl_xor_sync(0xffffffffu, ll, 2);
        lh += __shfl_xor_sync(0xffffffffu, lh, 1);
        lh += __shfl_xor_sync(0xffffffffu, lh, 2);
        float inv_lo = 1.f / ll, inv_hi = 1.f / lh;
        int r_lo = n0 + qrow + 16*mi + g, r_hi = r_lo + 8;
        #pragma unroll
        for (int c = 0; c < 8; ++c) {
            int col = h*64 + 8*c + 2*t;
            *(uint32_t*)(Og + (size_t)r_lo*CH + col) =
                packbf(o_acc[mi][c][0]*inv_lo, o_acc[mi][c][1]*inv_lo);
            *(uint32_t*)(Og + (size_t)r_hi*CH + col) =
                packbf(o_acc[mi][c][2]*inv_hi, o_acc[mi][c][3]*inv_hi);
        }
    }
}

// ---------------- 4) proj GEMM + bias + residual (per batch) -------------
__global__ __launch_bounds__(256) void gemm_proj(const float* __restrict__ bias,
                                                 const float* __restrict__ x,
                                                 float* __restrict__ out, int z) {
    extern __shared__ char gsm[];
    char* As = gsm;
    char* Bs = gsm + 3*GSTG;
    int m0 = blockIdx.y * 128, n0 = blockIdx.x * 128;
    float acc[4][4][4] = {};
    gemm_core(g_wp + (size_t)m0*512, g_o + (size_t)z*HW*CH + (size_t)n0*512,
              As, Bs, acc);

    int warp = threadIdx.x >> 5, lane = threadIdx.x & 31;
    int g = lane >> 2, t = lane & 3;
    int wm = (warp >> 2) * 64, wn = (warp & 3) * 32;

    #pragma unroll
    for (int mi = 0; mi < 4; ++mi) {
        #pragma unroll
        for (int rr = 0; rr < 2; ++rr) {
            int c = m0 + wm + 16*mi + g + rr*8;
            float bi = bias[c];
            size_t rowb = ((size_t)z*CH + c)*HW;
            #pragma unroll
            for (int nj = 0; nj < 4; ++nj) {
                int n = n0 + wn + 8*nj + 2*t;
                float2 xr = *(const float2*)(x + rowb + n);
                float2 o;
                o.x = acc[mi][nj][rr*2 + 0] + bi + xr.x;
                o.y = acc[mi][nj][rr*2 + 1] + bi + xr.y;
                *(float2*)(out + rowb + n) = o;
            }
        }
    }
}

// ---------------- launch: two-stream batch pipeline ----------------
extern "C" void kernel_launch(void* const* d_in, const int* in_sizes, int n_in,
                              void* d_out, int out_size) {
    const float* x      = (const float*)d_in[0];
    const float* norm_w = (const float*)d_in[1];
    const float* norm_b = (const float*)d_in[2];
    const float* qkv_w  = (const float*)d_in[3];
    const float* qkv_b  = (const float*)d_in[4];
    const float* proj_w = (const float*)d_in[5];
    const float* proj_b = (const float*)d_in[6];
    float* out = (float*)d_out;

    const int ASMEM = 64*QPITCH*2 + 4*ASTG;   // 70656
    const int GSMEM = 6*GSTG;                  // 61440
    cudaFuncSetAttribute(attn_kernel,
                         cudaFuncAttributeMaxDynamicSharedMemorySize, ASMEM);
    cudaFuncSetAttribute(gemm_qkv,
                         cudaFuncAttributeMaxDynamicSharedMemorySize, GSMEM);
    cudaFuncSetAttribute(gemm_proj,
                         cudaFuncAttributeMaxDynamicSharedMemorySize, GSMEM);

    static cudaStream_t s1 = nullptr;
    static cudaEvent_t evFork = nullptr, evJoin = nullptr;
    if (s1 == nullptr) {
        cudaStreamCreateWithFlags(&s1, cudaStreamNonBlocking);
        cudaEventCreateWithFlags(&evFork, cudaEventDisableTiming);
        cudaEventCreateWithFlags(&evJoin, cudaEventDisableTiming);
    }

    // shared prologue on the main (capture) stream
    gn_reduce<<<128 + 1024, 256>>>(x, qkv_w, proj_w);

    // fork: stream s1 handles batch 1
    cudaEventRecord(evFork, 0);
    cudaStreamWaitEvent(s1, evFork, 0);

    // batch 0 chain on main stream
    gn_apply<<<dim3(HW/64, NG), 256>>>(x, norm_w, norm_b, 0);
    gemm_qkv<<<dim3(HW/128, 12), 256, GSMEM>>>(qkv_b, 0);
    attn_kernel<<<dim3(HW/256, NH), 256, ASMEM>>>(0);
    gemm_proj<<<dim3(HW/128, 4), 256, GSMEM>>>(proj_b, x, out, 0);

    // batch 1 chain on s1
    gn_apply<<<dim3(HW/64, NG), 256, 0, s1>>>(x, norm_w, norm_b, 1);
    gemm_qkv<<<dim3(HW/128, 12), 256, GSMEM, s1>>>(qkv_b, 1);
    attn_kernel<<<dim3(HW/256, NH), 256, ASMEM, s1>>>(1);
    gemm_proj<<<dim3(HW/128, 4), 256, GSMEM, s1>>>(proj_b, x, out, 1);

    // join
    cudaEventRecord(evJoin, s1);
    cudaStreamWaitEvent(0, evJoin, 0);
}